// round 7
// baseline (speedup 1.0000x reference)
#include <cuda_runtime.h>

#define S_MAX 200000
#define N_MAX 250000
#define LB 64           // L == B == 64
#define ZCHUNK 512
#define IDXCAP 2048
// k_xz dynamic smem: XB 512*64 floats + WB 2*16*64 floats + (512+512+2048) ints
#define XZ_SMEM ((32768 + 2048) * 4 + (512 + 512 + IDXCAP) * 4)

// ---- device scratch (no allocations allowed) ----
__device__ float g_xT[(size_t)N_MAX * LB];    // x transposed [N,64]
__device__ float g_yT[(size_t)S_MAX * LB];    // y transposed [S,64]
__device__ float g_z[LB * LB];                // z stored l-major: z[l][b]
__device__ int   g_cm[S_MAX];                 // # added new nodes per master
__device__ int   g_cnt[N_MAX];                // # masters mapping to n
__device__ float g_bdacc[N_MAX];              // segment sum of bd_m
__device__ unsigned char g_added[N_MAX];
// CSR A: master m -> added new nodes n
__device__ int   g_offA[S_MAX];
__device__ int   g_fillA[S_MAX];
__device__ int   g_idxA[N_MAX];
// CSR Y: new node n -> masters m
__device__ int   g_offY[N_MAX];
__device__ int   g_fillY[N_MAX];
__device__ int   g_idxY[S_MAX];
// decoupled-lookback scan states
__device__ unsigned long long g_stA[512];
__device__ unsigned long long g_stB[512];

__global__ void k_xz(const float*, const int*, int);

// ---- streams/events (created pre-capture) ----
static cudaStream_t s2, s3;
static cudaEvent_t evRoot, evStats, evXT, evFY;
namespace {
struct InitStreams {
    InitStreams() {
        cudaStreamCreateWithFlags(&s2, cudaStreamNonBlocking);
        cudaStreamCreateWithFlags(&s3, cudaStreamNonBlocking);
        cudaEventCreateWithFlags(&evRoot, cudaEventDisableTiming);
        cudaEventCreateWithFlags(&evStats, cudaEventDisableTiming);
        cudaEventCreateWithFlags(&evXT, cudaEventDisableTiming);
        cudaEventCreateWithFlags(&evFY, cudaEventDisableTiming);
        cudaFuncSetAttribute(k_xz, cudaFuncAttributeMaxDynamicSharedMemorySize, XZ_SMEM);
    }
} s_init;
}

// ---------------- prep: clear everything + z bias ----------------
__global__ void k_prep(const float* __restrict__ be, int S, int N) {
    int i = blockIdx.x * blockDim.x + threadIdx.x;
    if (i < S) { g_cm[i] = 0; g_fillA[i] = 0; }
    if (i < N) { g_cnt[i] = 0; g_bdacc[i] = 0.f; g_fillY[i] = 0; }
    if (i < 512) { g_stA[i] = 0ULL; g_stB[i] = 0ULL; }
    if (i < LB * LB) g_z[i] = be[i >> 6];     // z[l][b] = be[l]
}

// ---------------- stats: added flags + c_m + cnt + bdacc ----------------
__global__ void k_stats(const int* __restrict__ nn_n, const int* __restrict__ nn_m,
                        const float* __restrict__ bd, int S, int N) {
    int i = blockIdx.x * blockDim.x + threadIdx.x;
    if (i < N) {
        int m = nn_n[i];
        int a = (nn_m[m] != i) ? 1 : 0;
        g_added[i] = (unsigned char)a;
        if (a) atomicAdd(&g_cm[m], 1);
    }
    if (i < S) {
        int nm = nn_m[i];
        atomicAdd(&g_cnt[nm], 1);
        atomicAdd(&g_bdacc[nm], bd[i]);
    }
}

// ---------------- x transpose [64,N] -> [N,64] ----------------
__global__ void k_xT(const float* __restrict__ x, int N) {
    __shared__ float tile[32][33];
    int n0 = blockIdx.x * 32;
    int b0 = blockIdx.y * 32;
    int tx = threadIdx.x, ty = threadIdx.y;   // 32 x 8
    #pragma unroll
    for (int i = 0; i < 32; i += 8) {
        int n = n0 + tx;
        tile[ty + i][tx] = (n < N) ? x[(size_t)(b0 + ty + i) * N + n] : 0.f;
    }
    __syncthreads();
    #pragma unroll
    for (int i = 0; i < 32; i += 8) {
        int n = n0 + ty + i;
        if (n < N) g_xT[(size_t)n * LB + b0 + tx] = tile[tx][ty + i];
    }
}

// ---------------- single-pass decoupled-lookback exclusive scan ----------------
// 256 threads, 1024 elements per block. state: lo32=value, hi32=flag(0/1/2).
__device__ __forceinline__ void scan_lb(const int* __restrict__ src, int* __restrict__ dst,
                                        unsigned long long* state, int len) {
    __shared__ int warpsum[8];
    __shared__ int s_exc;
    int t = threadIdx.x, b = blockIdx.x;
    int base = b * 1024 + t * 4;
    int v0 = 0, v1 = 0, v2 = 0, v3 = 0;
    if (base + 3 < len) {
        int4 q = *(const int4*)(src + base);
        v0 = q.x; v1 = q.y; v2 = q.z; v3 = q.w;
    } else {
        if (base     < len) v0 = src[base];
        if (base + 1 < len) v1 = src[base + 1];
        if (base + 2 < len) v2 = src[base + 2];
    }
    int sum4 = v0 + v1 + v2 + v3;
    int lane = t & 31, wid = t >> 5;
    int incl = sum4;
    #pragma unroll
    for (int d = 1; d < 32; d <<= 1) {
        int nb = __shfl_up_sync(0xffffffffu, incl, d);
        if (lane >= d) incl += nb;
    }
    if (lane == 31) warpsum[wid] = incl;
    __syncthreads();
    if (wid == 0) {
        int ws = (lane < 8) ? warpsum[lane] : 0;
        #pragma unroll
        for (int d = 1; d < 8; d <<= 1) {
            int nb = __shfl_up_sync(0xffffffffu, ws, d);
            if (lane >= d) ws += nb;
        }
        if (lane < 8) warpsum[lane] = ws;   // inclusive warp prefix
    }
    __syncthreads();
    int wbase = (wid == 0) ? 0 : warpsum[wid - 1];
    int texcl = wbase + incl - sum4;
    int total = warpsum[7];
    if (t == 0) {
        if (b == 0) {
            atomicExch(&state[0], (2ULL << 32) | (unsigned)total);
            s_exc = 0;
        } else {
            atomicExch(&state[b], (1ULL << 32) | (unsigned)total);
            long long exc = 0;
            int j = b - 1;
            while (true) {
                unsigned long long s;
                do { s = atomicAdd(&state[j], 0ULL); } while ((s >> 32) == 0ULL);
                exc += (int)(unsigned)s;
                if ((s >> 32) == 2ULL) break;
                j--;
            }
            atomicExch(&state[b], (2ULL << 32) | (unsigned)(exc + total));
            s_exc = (int)exc;
        }
    }
    __syncthreads();
    int e = s_exc + texcl;
    if (base     < len) dst[base]     = e;
    if (base + 1 < len) dst[base + 1] = e + v0;
    if (base + 2 < len) dst[base + 2] = e + v0 + v1;
    if (base + 3 < len) dst[base + 3] = e + v0 + v1 + v2;
}

__global__ void __launch_bounds__(256) k_scanA(int S) { scan_lb(g_cm,  g_offA, g_stA, S); }
__global__ void __launch_bounds__(256) k_scanB(int N) { scan_lb(g_cnt, g_offY, g_stB, N); }

// ---------------- CSR index fills ----------------
__global__ void k_fillA(const int* __restrict__ nn_n, int N) {
    int i = blockIdx.x * blockDim.x + threadIdx.x;
    if (i < N && g_added[i]) {
        int m = nn_n[i];
        int pos = g_offA[m] + atomicAdd(&g_fillA[m], 1);
        g_idxA[pos] = i;
    }
}
__global__ void k_fillY(const int* __restrict__ nn_m, int S) {
    int i = blockIdx.x * blockDim.x + threadIdx.x;
    if (i < S) {
        int nm = nn_m[i];
        int pos = g_offY[nm] + atomicAdd(&g_fillY[nm], 1);
        g_idxY[pos] = i;
    }
}

// ---------------- fused xagg + z GEMM ----------------
// Phase 1: block gathers its 512 aggregated+scaled x rows into 128KB smem.
// Phase 2: streaming GEMM z += We[k0:k0+512]^T @ XB, W double-buffered.
__global__ void __launch_bounds__(256) k_xz(const float* __restrict__ We,
                                            const int* __restrict__ nn_m, int S) {
    extern __shared__ float SM[];
    float* XB = SM;                         // 32768 floats
    float* WB = SM + 32768;                 // 2048 floats (2 x 16 x 64)
    int* scm  = (int*)(WB + 2048);
    int* soff = scm + 512;
    int* sidx = soff + 512;                 // IDXCAP
    int tid = threadIdx.x;
    int k0 = blockIdx.x * ZCHUNK;
    int nrows = S - k0; if (nrows > ZCHUNK) nrows = ZCHUNK;

    for (int i = tid; i < nrows; i += 256) {
        scm[i]  = g_cm[k0 + i];
        soff[i] = g_offA[k0 + i];
    }
    __syncthreads();
    int eBase = soff[0];
    int E = soff[nrows - 1] + scm[nrows - 1] - eBase;
    bool fits = (E <= IDXCAP);
    if (fits)
        for (int i = tid; i < E; i += 256) sidx[i] = g_idxA[eBase + i];
    __syncthreads();

    // gather: half-warp per row, float4 per lane
    int hw = tid >> 4, l16 = tid & 15;
    for (int r = hw; r < ZCHUNK; r += 16) {
        float4 acc = make_float4(0.f, 0.f, 0.f, 0.f);
        if (r < nrows) {
            int k = k0 + r;
            acc = *(const float4*)&g_xT[(size_t)nn_m[k] * 64 + l16 * 4];
            int cm = scm[r];
            int o = soff[r] - eBase;
            for (int s = 0; s < cm; s++) {
                int n = fits ? sidx[o + s] : g_idxA[eBase + o + s];
                float4 v = *(const float4*)&g_xT[(size_t)n * 64 + l16 * 4];
                acc.x += v.x; acc.y += v.y; acc.z += v.z; acc.w += v.w;
            }
            float sc = 1.0f / (float)(cm + 1);
            acc.x *= sc; acc.y *= sc; acc.z *= sc; acc.w *= sc;
        }
        *(float4*)&XB[r * 64 + l16 * 4] = acc;
    }
    __syncthreads();

    // GEMM
    int tx = tid & 15, ty = tid >> 4;
    int row = tid >> 4, col4 = (tid & 15) * 4;
    float acc[4][4];
    #pragma unroll
    for (int i = 0; i < 4; i++)
        #pragma unroll
        for (int j = 0; j < 4; j++) acc[i][j] = 0.f;

    {
        int k = k0 + row;
        float4 w4 = make_float4(0.f, 0.f, 0.f, 0.f);
        if (k < S) w4 = *(const float4*)&We[(size_t)k * 64 + col4];
        *(float4*)&WB[row * 64 + col4] = w4;
    }
    __syncthreads();

    int cur = 0;
    for (int kk = 16; kk <= ZCHUNK; kk += 16) {
        float4 nw = make_float4(0.f, 0.f, 0.f, 0.f);
        if (kk < ZCHUNK) {
            int k = k0 + kk + row;
            if (k < S) nw = *(const float4*)&We[(size_t)k * 64 + col4];
        }
        const float* xb = XB + (kk - 16) * 64;
        const float* wb = WB + cur * 1024;
        #pragma unroll
        for (int g = 0; g < 16; g++) {
            float4 xv = *(const float4*)&xb[g * 64 + ty * 4];
            float4 wv = *(const float4*)&wb[g * 64 + tx * 4];
            acc[0][0] += xv.x * wv.x; acc[0][1] += xv.x * wv.y; acc[0][2] += xv.x * wv.z; acc[0][3] += xv.x * wv.w;
            acc[1][0] += xv.y * wv.x; acc[1][1] += xv.y * wv.y; acc[1][2] += xv.y * wv.z; acc[1][3] += xv.y * wv.w;
            acc[2][0] += xv.z * wv.x; acc[2][1] += xv.z * wv.y; acc[2][2] += xv.z * wv.z; acc[2][3] += xv.z * wv.w;
            acc[3][0] += xv.w * wv.x; acc[3][1] += xv.w * wv.y; acc[3][2] += xv.w * wv.z; acc[3][3] += xv.w * wv.w;
        }
        if (kk < ZCHUNK) *(float4*)&WB[(cur ^ 1) * 1024 + row * 64 + col4] = nw;
        __syncthreads();
        cur ^= 1;
    }

    #pragma unroll
    for (int i = 0; i < 4; i++)
        #pragma unroll
        for (int j = 0; j < 4; j++)
            atomicAdd(&g_z[(tx * 4 + j) * 64 + (ty * 4 + i)], acc[i][j]);
}

// ---------------- y = z @ Wd (per 128-column tile), store yT ----------------
__global__ void __launch_bounds__(256) k_y1(const float* __restrict__ Wd, int S) {
    __shared__ float sbuf[128 * 68];
    int tid = threadIdx.x;
    int m0 = blockIdx.x * 128;
    for (int i = tid; i < 4096; i += 256) sbuf[i] = g_z[i];
    __syncthreads();

    int tx = tid & 31, ty = tid >> 5;
    int mbase = m0 + tx * 4;
    bool valid = (mbase + 4) <= S;

    float acc[8][4];
    #pragma unroll
    for (int bi = 0; bi < 8; bi++)
        #pragma unroll
        for (int mj = 0; mj < 4; mj++) acc[bi][mj] = 0.f;

    #pragma unroll 4
    for (int l = 0; l < 64; l++) {
        float4 wv = valid ? *(const float4*)&Wd[(size_t)l * S + mbase]
                          : make_float4(0.f, 0.f, 0.f, 0.f);
        float4 z0 = *(const float4*)&sbuf[l * 64 + ty * 8];
        float4 z1 = *(const float4*)&sbuf[l * 64 + ty * 8 + 4];
        float zb[8] = {z0.x, z0.y, z0.z, z0.w, z1.x, z1.y, z1.z, z1.w};
        #pragma unroll
        for (int bi = 0; bi < 8; bi++) {
            acc[bi][0] += zb[bi] * wv.x;
            acc[bi][1] += zb[bi] * wv.y;
            acc[bi][2] += zb[bi] * wv.z;
            acc[bi][3] += zb[bi] * wv.w;
        }
    }
    __syncthreads();

    #pragma unroll
    for (int bi = 0; bi < 8; bi++)
        #pragma unroll
        for (int mj = 0; mj < 4; mj++)
            sbuf[(tx * 4 + mj) * 68 + (ty * 8 + bi)] = acc[bi][mj];
    __syncthreads();

    int cr = tid >> 4;
    int cc = (tid & 15) * 4;
    for (int rr = cr; rr < 128; rr += 16) {
        int m = m0 + rr;
        if (m < S)
            *(float4*)&g_yT[(size_t)m * 64 + cc] = *(const float4*)&sbuf[rr * 68 + cc];
    }
}

// ---------------- finalize: 8 threads/n CSR gather, scale, bias, transpose-store ----------------
__global__ void __launch_bounds__(256) k_y2(float* __restrict__ out,
                                            const float* __restrict__ bd,
                                            const int* __restrict__ nn_n, int N) {
    __shared__ float t[32][65];
    int n0 = blockIdx.x * 32;
    int tid = threadIdx.x;
    int r = tid >> 3;               // n within tile 0..31
    int q = (tid & 7) * 8;          // 8 b-columns per thread
    int n = n0 + r;
    if (n < N) {
        int a = g_added[n];
        int mstar = nn_n[n];
        int cnt = g_cnt[n];
        float dn = (float)(cnt + a);
        if (dn < 1.f) dn = 1.f;
        float inv = 1.0f / dn;
        float bdn = (g_bdacc[n] + (a ? bd[mstar] : 0.f)) * inv;

        float acc[8];
        #pragma unroll
        for (int j = 0; j < 8; j++) acc[j] = 0.f;

        int o = g_offY[n];
        for (int s = 0; s < cnt; s++) {
            int m = g_idxY[o + s];
            const float* yr = g_yT + (size_t)m * 64 + q;
            float4 v0 = *(const float4*)(yr);
            float4 v1 = *(const float4*)(yr + 4);
            acc[0] += v0.x; acc[1] += v0.y; acc[2] += v0.z; acc[3] += v0.w;
            acc[4] += v1.x; acc[5] += v1.y; acc[6] += v1.z; acc[7] += v1.w;
        }
        if (a) {
            const float* yr = g_yT + (size_t)mstar * 64 + q;
            float4 v0 = *(const float4*)(yr);
            float4 v1 = *(const float4*)(yr + 4);
            acc[0] += v0.x; acc[1] += v0.y; acc[2] += v0.z; acc[3] += v0.w;
            acc[4] += v1.x; acc[5] += v1.y; acc[6] += v1.z; acc[7] += v1.w;
        }
        #pragma unroll
        for (int j = 0; j < 8; j++) t[r][q + j] = acc[j] * inv + bdn;
    }
    __syncthreads();
    int cidx = tid & 31;
    if (n0 + cidx < N) {
        #pragma unroll
        for (int b = tid >> 5; b < 64; b += 8)
            out[(size_t)b * N + n0 + cidx] = t[cidx][b];
    }
}

extern "C" void kernel_launch(void* const* d_in, const int* in_sizes, int n_in,
                              void* d_out, int out_size) {
    const float* We   = (const float*)d_in[0];
    const float* be   = (const float*)d_in[1];
    const float* Wd   = (const float*)d_in[2];
    const float* bd   = (const float*)d_in[3];
    const float* x    = (const float*)d_in[4];
    const int*   nn_n = (const int*)d_in[5];
    const int*   nn_m = (const int*)d_in[6];
    int S = in_sizes[3];   // bd_m has S elements
    int N = in_sizes[5];   // nn_n has N elements
    float* out = (float*)d_out;

    int mx = (N > S) ? N : S;

    // fork: xT on s2 (depends only on x)
    cudaEventRecord(evRoot, 0);
    cudaStreamWaitEvent(s2, evRoot, 0);
    {
        dim3 tb(32, 8);
        dim3 tg((N + 31) / 32, 2);
        k_xT<<<tg, tb, 0, s2>>>(x, N);
    }
    cudaEventRecord(evXT, s2);

    // main chain
    k_prep<<<(mx + 255) / 256, 256>>>(be, S, N);
    k_stats<<<(mx + 255) / 256, 256>>>(nn_n, nn_m, bd, S, N);
    cudaEventRecord(evStats, 0);

    k_scanA<<<(S + 1023) / 1024, 256>>>(S);
    k_fillA<<<(N + 255) / 256, 256>>>(nn_n, N);

    cudaStreamWaitEvent(0, evXT, 0);
    k_xz<<<(S + ZCHUNK - 1) / ZCHUNK, 256, XZ_SMEM>>>(We, nn_m, S);
    k_y1<<<(S + 127) / 128, 256>>>(Wd, S);

    // side chain on s3: CSR-Y build (only needed by k_y2)
    cudaStreamWaitEvent(s3, evStats, 0);
    k_scanB<<<(N + 1023) / 1024, 256, 0, s3>>>(N);
    k_fillY<<<(S + 255) / 256, 256, 0, s3>>>(nn_m, S);
    cudaEventRecord(evFY, s3);

    cudaStreamWaitEvent(0, evFY, 0);
    k_y2<<<(N + 31) / 32, 256>>>(out, bd, nn_n, N);
}

// round 9
// speedup vs baseline: 1.6665x; 1.6665x over previous
#include <cuda_runtime.h>
#include <cuda_bf16.h>
#include <mma.h>
#include <cstdint>

using namespace nvcuda;

#define S_MAX 200000
#define N_MAX 250000
#define LB 64           // L == B == 64
#define KSPAN 512       // K-range per k_zt block
#define KSUB 64         // staged sub-slab

// ---- device scratch (no allocations allowed) ----
__device__ float g_xT[(size_t)N_MAX * LB];    // x transposed [N,64]
__device__ float g_xagg[(size_t)S_MAX * LB];  // aggregated+scaled x per master [S,64]
__device__ float g_yT[(size_t)S_MAX * LB];    // y transposed [S,64]
__device__ float g_z[LB * LB];                // z stored l-major: z[l][b]
__device__ int   g_cm[S_MAX];
__device__ int   g_cnt[N_MAX];
__device__ float g_bdacc[N_MAX];
__device__ unsigned char g_added[N_MAX];
__device__ int   g_offA[S_MAX];
__device__ int   g_fillA[S_MAX];
__device__ int   g_idxA[N_MAX];
__device__ int   g_offY[N_MAX];
__device__ int   g_fillY[N_MAX];
__device__ int   g_idxY[S_MAX];
__device__ int   g_bsumA[1024];
__device__ int   g_boffA[1024];
__device__ int   g_bsumB[1024];
__device__ int   g_boffB[1024];

__device__ __forceinline__ void bsplit(float v, __nv_bfloat16& h, __nv_bfloat16& l) {
    h = __float2bfloat16(v);
    l = __float2bfloat16(v - __bfloat162float(h));
}

// k_zt dyn smem: 2 buffers x { WeH, WeL, XH, XL } each 64x72 bf16 (9216 B) = 73728 B
#define ZT_SMEM 73728
// k_y1m dyn smem: AH/AL 64x136 bf16 (17408 B each), BH/BL 64x72 bf16 (9216 B each) = 53248 B
#define Y1_SMEM 53248

__global__ void k_zt(const float*, int);
__global__ void k_y1m(const float*, int);

// ---- streams/events (created pre-capture) ----
static cudaStream_t s2, s3;
static cudaEvent_t evRoot, evStats, evXT, evFY;
namespace {
struct InitStreams {
    InitStreams() {
        cudaStreamCreateWithFlags(&s2, cudaStreamNonBlocking);
        cudaStreamCreateWithFlags(&s3, cudaStreamNonBlocking);
        cudaEventCreateWithFlags(&evRoot, cudaEventDisableTiming);
        cudaEventCreateWithFlags(&evStats, cudaEventDisableTiming);
        cudaEventCreateWithFlags(&evXT, cudaEventDisableTiming);
        cudaEventCreateWithFlags(&evFY, cudaEventDisableTiming);
        cudaFuncSetAttribute(k_zt,  cudaFuncAttributeMaxDynamicSharedMemorySize, ZT_SMEM);
        cudaFuncSetAttribute(k_y1m, cudaFuncAttributeMaxDynamicSharedMemorySize, Y1_SMEM);
    }
} s_init;
}

// ---------------- prep ----------------
__global__ void k_prep(const float* __restrict__ be, int S, int N) {
    int i = blockIdx.x * blockDim.x + threadIdx.x;
    if (i < S) { g_cm[i] = 0; g_fillA[i] = 0; }
    if (i < N) { g_cnt[i] = 0; g_bdacc[i] = 0.f; g_fillY[i] = 0; }
    if (i < LB * LB) g_z[i] = be[i >> 6];
}

// ---------------- stats ----------------
__global__ void k_stats(const int* __restrict__ nn_n, const int* __restrict__ nn_m,
                        const float* __restrict__ bd, int S, int N) {
    int i = blockIdx.x * blockDim.x + threadIdx.x;
    if (i < N) {
        int m = nn_n[i];
        int a = (nn_m[m] != i) ? 1 : 0;
        g_added[i] = (unsigned char)a;
        if (a) atomicAdd(&g_cm[m], 1);
    }
    if (i < S) {
        int nm = nn_m[i];
        atomicAdd(&g_cnt[nm], 1);
        atomicAdd(&g_bdacc[nm], bd[i]);
    }
}

// ---------------- x transpose ----------------
__global__ void k_xT(const float* __restrict__ x, int N) {
    __shared__ float tile[32][33];
    int n0 = blockIdx.x * 32;
    int b0 = blockIdx.y * 32;
    int tx = threadIdx.x, ty = threadIdx.y;
    #pragma unroll
    for (int i = 0; i < 32; i += 8) {
        int n = n0 + tx;
        tile[ty + i][tx] = (n < N) ? x[(size_t)(b0 + ty + i) * N + n] : 0.f;
    }
    __syncthreads();
    #pragma unroll
    for (int i = 0; i < 32; i += 8) {
        int n = n0 + ty + i;
        if (n < N) g_xT[(size_t)n * LB + b0 + tx] = tile[tx][ty + i];
    }
}

// ---------------- scans (round-6 3-kernel chains) ----------------
__global__ void k_scan1A(int S) {
    __shared__ int sd[256];
    int t = threadIdx.x;
    int n = blockIdx.x * 256 + t;
    sd[t] = (n < S) ? g_cm[n] : 0;
    __syncthreads();
    #pragma unroll
    for (int d = 128; d > 0; d >>= 1) { if (t < d) sd[t] += sd[t + d]; __syncthreads(); }
    if (t == 0) g_bsumA[blockIdx.x] = sd[0];
}
__global__ void k_scan1B(int N) {
    __shared__ int sd[256];
    int t = threadIdx.x;
    int n = blockIdx.x * 256 + t;
    sd[t] = (n < N) ? g_cnt[n] : 0;
    __syncthreads();
    #pragma unroll
    for (int d = 128; d > 0; d >>= 1) { if (t < d) sd[t] += sd[t + d]; __syncthreads(); }
    if (t == 0) g_bsumB[blockIdx.x] = sd[0];
}
__global__ void k_scan2A(int nch) {
    __shared__ int sd[1024];
    int t = threadIdx.x;
    int v = (t < nch) ? g_bsumA[t] : 0;
    sd[t] = v;
    __syncthreads();
    #pragma unroll
    for (int d = 1; d < 1024; d <<= 1) {
        int add = (t >= d) ? sd[t - d] : 0;
        __syncthreads(); sd[t] += add; __syncthreads();
    }
    if (t < nch) g_boffA[t] = sd[t] - v;
}
__global__ void k_scan2B(int nch) {
    __shared__ int sd[1024];
    int t = threadIdx.x;
    int v = (t < nch) ? g_bsumB[t] : 0;
    sd[t] = v;
    __syncthreads();
    #pragma unroll
    for (int d = 1; d < 1024; d <<= 1) {
        int add = (t >= d) ? sd[t - d] : 0;
        __syncthreads(); sd[t] += add; __syncthreads();
    }
    if (t < nch) g_boffB[t] = sd[t] - v;
}
__global__ void k_scan3A(int S) {
    __shared__ int sd[256];
    int t = threadIdx.x;
    int n = blockIdx.x * 256 + t;
    int v = (n < S) ? g_cm[n] : 0;
    sd[t] = v;
    __syncthreads();
    #pragma unroll
    for (int d = 1; d < 256; d <<= 1) {
        int add = (t >= d) ? sd[t - d] : 0;
        __syncthreads(); sd[t] += add; __syncthreads();
    }
    if (n < S) g_offA[n] = g_boffA[blockIdx.x] + sd[t] - v;
}
__global__ void k_scan3B(int N) {
    __shared__ int sd[256];
    int t = threadIdx.x;
    int n = blockIdx.x * 256 + t;
    int v = (n < N) ? g_cnt[n] : 0;
    sd[t] = v;
    __syncthreads();
    #pragma unroll
    for (int d = 1; d < 256; d <<= 1) {
        int add = (t >= d) ? sd[t - d] : 0;
        __syncthreads(); sd[t] += add; __syncthreads();
    }
    if (n < N) g_offY[n] = g_boffB[blockIdx.x] + sd[t] - v;
}

// ---------------- CSR fills ----------------
__global__ void k_fillA(const int* __restrict__ nn_n, int N) {
    int i = blockIdx.x * blockDim.x + threadIdx.x;
    if (i < N && g_added[i]) {
        int m = nn_n[i];
        int pos = g_offA[m] + atomicAdd(&g_fillA[m], 1);
        g_idxA[pos] = i;
    }
}
__global__ void k_fillY(const int* __restrict__ nn_m, int S) {
    int i = blockIdx.x * blockDim.x + threadIdx.x;
    if (i < S) {
        int nm = nn_m[i];
        int pos = g_offY[nm] + atomicAdd(&g_fillY[nm], 1);
        g_idxY[pos] = i;
    }
}

// ---------------- Xagg ----------------
__global__ void __launch_bounds__(256) k_xagg(const int* __restrict__ nn_m, int S) {
    int w = (blockIdx.x * blockDim.x + threadIdx.x) >> 5;
    int lane = threadIdx.x & 31;
    if (w >= S) return;
    int h = lane >> 4;
    int l16 = lane & 15;
    int cm = g_cm[w];
    float scale = 1.0f / (float)(cm + 1);
    float4 acc = make_float4(0.f, 0.f, 0.f, 0.f);
    if (h == 0)
        acc = *(const float4*)&g_xT[(size_t)nn_m[w] * 64 + l16 * 4];
    int o = g_offA[w];
    for (int s = h; s < cm; s += 2) {
        int n = g_idxA[o + s];
        float4 v = *(const float4*)&g_xT[(size_t)n * 64 + l16 * 4];
        acc.x += v.x; acc.y += v.y; acc.z += v.z; acc.w += v.w;
    }
    acc.x += __shfl_xor_sync(0xffffffffu, acc.x, 16);
    acc.y += __shfl_xor_sync(0xffffffffu, acc.y, 16);
    acc.z += __shfl_xor_sync(0xffffffffu, acc.z, 16);
    acc.w += __shfl_xor_sync(0xffffffffu, acc.w, 16);
    if (h == 0) {
        acc.x *= scale; acc.y *= scale; acc.z *= scale; acc.w *= scale;
        *(float4*)&g_xagg[(size_t)w * 64 + l16 * 4] = acc;
    }
}

// ---------------- z GEMM via WMMA split-bf16 ----------------
// z[l][b] = sum_k We[k][l] * Xagg[k][b].
// A = We slab [k][72l] col_major (addr(m=l,k)=l+k*72), B = Xagg slab [k][72b] row_major.
// Double-buffered 64-K sub-slabs; 8 warps x 2 output tiles; flush via 4096 atomics.
__device__ __forceinline__ void zt_stage(__nv_bfloat16* buf, const float* __restrict__ We,
                                         int kbase, int S, int tid) {
    __nv_bfloat16* WeH = buf;
    __nv_bfloat16* WeL = buf + 4608;
    __nv_bfloat16* XH  = buf + 9216;
    __nv_bfloat16* XL  = buf + 13824;
    int r = tid >> 2;            // 0..63
    int c = (tid & 3) * 16;
    int k = kbase + r;
    bool val = (k < S);
    #pragma unroll
    for (int j = 0; j < 16; j += 4) {
        float4 w = val ? *(const float4*)&We[(size_t)k * 64 + c + j]
                       : make_float4(0.f, 0.f, 0.f, 0.f);
        float4 xx = val ? *(const float4*)&g_xagg[(size_t)k * 64 + c + j]
                        : make_float4(0.f, 0.f, 0.f, 0.f);
        float wv[4] = {w.x, w.y, w.z, w.w};
        float xv[4] = {xx.x, xx.y, xx.z, xx.w};
        #pragma unroll
        for (int u = 0; u < 4; u++) {
            __nv_bfloat16 h, l;
            bsplit(wv[u], h, l);
            WeH[r * 72 + c + j + u] = h; WeL[r * 72 + c + j + u] = l;
            bsplit(xv[u], h, l);
            XH[r * 72 + c + j + u] = h;  XL[r * 72 + c + j + u] = l;
        }
    }
}

__global__ void __launch_bounds__(256) k_zt(const float* __restrict__ We, int S) {
    extern __shared__ char smraw[];
    __nv_bfloat16* smz = (__nv_bfloat16*)smraw;   // 2 buffers x 18432 elems
    int tid = threadIdx.x;
    int warp = tid >> 5;
    int k0 = blockIdx.x * KSPAN;

    wmma::fragment<wmma::accumulator, 16, 16, 16, float> acc[2];
    wmma::fill_fragment(acc[0], 0.f);
    wmma::fill_fragment(acc[1], 0.f);
    int lt = warp >> 1;              // l-tile 0..3
    int bt0 = (warp & 1) * 2;        // b-tiles bt0, bt0+1

    zt_stage(smz, We, k0, S, tid);
    __syncthreads();

    const int NSUB = KSPAN / KSUB;
    for (int s = 0; s < NSUB; s++) {
        if (s + 1 < NSUB)
            zt_stage(smz + ((s + 1) & 1) * 18432, We, k0 + (s + 1) * KSUB, S, tid);
        __nv_bfloat16* buf = smz + (s & 1) * 18432;
        __nv_bfloat16* WeH = buf;
        __nv_bfloat16* WeL = buf + 4608;
        __nv_bfloat16* XH  = buf + 9216;
        __nv_bfloat16* XL  = buf + 13824;
        #pragma unroll
        for (int kt = 0; kt < 4; kt++) {
            wmma::fragment<wmma::matrix_a, 16, 16, 16, __nv_bfloat16, wmma::col_major> aH, aL;
            wmma::load_matrix_sync(aH, WeH + kt * 16 * 72 + lt * 16, 72);
            wmma::load_matrix_sync(aL, WeL + kt * 16 * 72 + lt * 16, 72);
            #pragma unroll
            for (int q = 0; q < 2; q++) {
                int bt = bt0 + q;
                wmma::fragment<wmma::matrix_b, 16, 16, 16, __nv_bfloat16, wmma::row_major> bH, bL;
                wmma::load_matrix_sync(bH, XH + kt * 16 * 72 + bt * 16, 72);
                wmma::load_matrix_sync(bL, XL + kt * 16 * 72 + bt * 16, 72);
                wmma::mma_sync(acc[q], aH, bH, acc[q]);
                wmma::mma_sync(acc[q], aH, bL, acc[q]);
                wmma::mma_sync(acc[q], aL, bH, acc[q]);
            }
        }
        __syncthreads();
    }

    // flush: store fragments to smem f32 [64][64], then atomics
    float* zz = (float*)smraw;
    wmma::store_matrix_sync(zz + (lt * 16) * 64 + bt0 * 16, acc[0], 64, wmma::mem_row_major);
    wmma::store_matrix_sync(zz + (lt * 16) * 64 + (bt0 + 1) * 16, acc[1], 64, wmma::mem_row_major);
    __syncthreads();
    int base = tid * 16;
    #pragma unroll
    for (int i = 0; i < 16; i++)
        atomicAdd(&g_z[base + i], zz[base + i]);
}

// ---------------- y = z @ Wd via WMMA split-bf16 ----------------
// y[m][b] = sum_l Wd[l][m] * z[l][b].
// A = Wd tile [l][136m] col_major, B = z [l][72b] row_major. Direct layouts, no transpose.
__global__ void __launch_bounds__(256) k_y1m(const float* __restrict__ Wd, int S) {
    extern __shared__ char smraw[];
    __nv_bfloat16* AH = (__nv_bfloat16*)smraw;        // 64*136
    __nv_bfloat16* AL = AH + 8704;
    __nv_bfloat16* BH = AH + 17408;                   // 64*72
    __nv_bfloat16* BL = AH + 22016;
    int tid = threadIdx.x;
    int m0 = blockIdx.x * 128;

    // stage z -> B hi/lo
    for (int i = tid * 4; i < 4096; i += 1024) {
        float4 v = *(const float4*)&g_z[i];
        int l = i >> 6, b = i & 63;
        float vv[4] = {v.x, v.y, v.z, v.w};
        #pragma unroll
        for (int u = 0; u < 4; u++) {
            __nv_bfloat16 h, lo;
            bsplit(vv[u], h, lo);
            BH[l * 72 + b + u] = h;
            BL[l * 72 + b + u] = lo;
        }
    }
    // stage Wd -> A hi/lo: A[l][m], coalesced reads, conflict-free writes
    {
        int mm = tid & 127;
        int m = m0 + mm;
        bool val = (m < S);
        for (int l = tid >> 7; l < 64; l += 2) {
            float w = val ? Wd[(size_t)l * S + m] : 0.f;
            __nv_bfloat16 h, lo;
            bsplit(w, h, lo);
            AH[l * 136 + mm] = h;
            AL[l * 136 + mm] = lo;
        }
    }
    __syncthreads();

    int warp = tid >> 5;              // m-tile 0..7
    int mt16 = m0 + warp * 16;
    wmma::fragment<wmma::accumulator, 16, 16, 16, float> acc[4];
    #pragma unroll
    for (int q = 0; q < 4; q++) wmma::fill_fragment(acc[q], 0.f);

    #pragma unroll
    for (int kt = 0; kt < 4; kt++) {
        wmma::fragment<wmma::matrix_a, 16, 16, 16, __nv_bfloat16, wmma::col_major> aH, aL;
        wmma::load_matrix_sync(aH, AH + kt * 16 * 136 + warp * 16, 136);
        wmma::load_matrix_sync(aL, AL + kt * 16 * 136 + warp * 16, 136);
        #pragma unroll
        for (int bt = 0; bt < 4; bt++) {
            wmma::fragment<wmma::matrix_b, 16, 16, 16, __nv_bfloat16, wmma::row_major> bH, bL;
            wmma::load_matrix_sync(bH, BH + kt * 16 * 72 + bt * 16, 72);
            wmma::load_matrix_sync(bL, BL + kt * 16 * 72 + bt * 16, 72);
            wmma::mma_sync(acc[bt], aH, bH, acc[bt]);
            wmma::mma_sync(acc[bt], aH, bL, acc[bt]);
            wmma::mma_sync(acc[bt], aL, bH, acc[bt]);
        }
    }

    if (mt16 < S) {   // 16 | S: tile all-or-nothing
        #pragma unroll
        for (int bt = 0; bt < 4; bt++)
            wmma::store_matrix_sync(&g_yT[(size_t)mt16 * 64 + bt * 16], acc[bt], 64,
                                    wmma::mem_row_major);
    }
}

// ---------------- finalize ----------------
__global__ void __launch_bounds__(256) k_y2(float* __restrict__ out,
                                            const float* __restrict__ bd,
                                            const int* __restrict__ nn_n, int N) {
    __shared__ float t[32][65];
    int n0 = blockIdx.x * 32;
    int tid = threadIdx.x;
    int r = tid >> 3;
    int q = (tid & 7) * 8;
    int n = n0 + r;
    if (n < N) {
        int a = g_added[n];
        int mstar = nn_n[n];
        int cnt = g_cnt[n];
        float dn = (float)(cnt + a);
        if (dn < 1.f) dn = 1.f;
        float inv = 1.0f / dn;
        float bdn = (g_bdacc[n] + (a ? bd[mstar] : 0.f)) * inv;

        float acc[8];
        #pragma unroll
        for (int j = 0; j < 8; j++) acc[j] = 0.f;

        int o = g_offY[n];
        for (int s = 0; s < cnt; s++) {
            int m = g_idxY[o + s];
            const float* yr = g_yT + (size_t)m * 64 + q;
            float4 v0 = *(const float4*)(yr);
            float4 v1 = *(const float4*)(yr + 4);
            acc[0] += v0.x; acc[1] += v0.y; acc[2] += v0.z; acc[3] += v0.w;
            acc[4] += v1.x; acc[5] += v1.y; acc[6] += v1.z; acc[7] += v1.w;
        }
        if (a) {
            const float* yr = g_yT + (size_t)mstar * 64 + q;
            float4 v0 = *(const float4*)(yr);
            float4 v1 = *(const float4*)(yr + 4);
            acc[0] += v0.x; acc[1] += v0.y; acc[2] += v0.z; acc[3] += v0.w;
            acc[4] += v1.x; acc[5] += v1.y; acc[6] += v1.z; acc[7] += v1.w;
        }
        #pragma unroll
        for (int j = 0; j < 8; j++) t[r][q + j] = acc[j] * inv + bdn;
    }
    __syncthreads();
    int cidx = tid & 31;
    if (n0 + cidx < N) {
        #pragma unroll
        for (int b = tid >> 5; b < 64; b += 8)
            out[(size_t)b * N + n0 + cidx] = t[cidx][b];
    }
}

extern "C" void kernel_launch(void* const* d_in, const int* in_sizes, int n_in,
                              void* d_out, int out_size) {
    const float* We   = (const float*)d_in[0];
    const float* be   = (const float*)d_in[1];
    const float* Wd   = (const float*)d_in[2];
    const float* bd   = (const float*)d_in[3];
    const float* x    = (const float*)d_in[4];
    const int*   nn_n = (const int*)d_in[5];
    const int*   nn_m = (const int*)d_in[6];
    int S = in_sizes[3];
    int N = in_sizes[5];
    float* out = (float*)d_out;

    int mx = (N > S) ? N : S;
    int cA = (S + 255) / 256;
    int cB = (N + 255) / 256;

    // fork: xT on s2 (depends only on x)
    cudaEventRecord(evRoot, 0);
    cudaStreamWaitEvent(s2, evRoot, 0);
    {
        dim3 tb(32, 8);
        dim3 tg((N + 31) / 32, 2);
        k_xT<<<tg, tb, 0, s2>>>(x, N);
    }
    cudaEventRecord(evXT, s2);

    // main chain
    k_prep<<<(mx + 255) / 256, 256>>>(be, S, N);
    k_stats<<<(mx + 255) / 256, 256>>>(nn_n, nn_m, bd, S, N);
    cudaEventRecord(evStats, 0);

    // side chain on s3: CSR-Y build (only needed by k_y2)
    cudaStreamWaitEvent(s3, evStats, 0);
    k_scan1B<<<cB, 256, 0, s3>>>(N);
    k_scan2B<<<1, 1024, 0, s3>>>(cB);
    k_scan3B<<<cB, 256, 0, s3>>>(N);
    k_fillY<<<(S + 255) / 256, 256, 0, s3>>>(nn_m, S);
    cudaEventRecord(evFY, s3);

    // main chain: CSR-A -> xagg -> z(wmma) -> y1(wmma)
    k_scan1A<<<cA, 256>>>(S);
    k_scan2A<<<1, 1024>>>(cA);
    k_scan3A<<<cA, 256>>>(S);
    k_fillA<<<(N + 255) / 256, 256>>>(nn_n, N);

    cudaStreamWaitEvent(0, evXT, 0);
    k_xagg<<<(S * 32 + 255) / 256, 256>>>(nn_m, S);
    k_zt<<<(S + KSPAN - 1) / KSPAN, 256, ZT_SMEM>>>(We, S);
    k_y1m<<<(S + 127) / 128, 256, Y1_SMEM>>>(Wd, S);

    cudaStreamWaitEvent(0, evFY, 0);
    k_y2<<<(N + 31) / 32, 256>>>(out, bd, nn_n, N);
}